// round 15
// baseline (speedup 1.0000x reference)
#include <cuda_runtime.h>
#include <cuda_fp16.h>
#include <cstdint>

#define NT       256
#define TB       64
#define BATCH    8192
#define T_STEPS  128

// SMEM byte layout
//  A  : 6kb x 8wm x 2mt x 8g x 4tq units of 16B = 49152 B   (kb 0,1 = x ; kb 2..5 = h)
//  Bh : 2 grp x 2 phase x (4 kb2 x 32n x 32B) = 16384 B
//  X  : 2 grp x 3 buf   x (2 kbx x 32n x 32B) = 12288 B
//  H  : 64 x 68 floats (FC staging)           = 17408 B
#define A_BYTES   49152
#define BH_OFF    A_BYTES
#define X_OFF     (BH_OFF + 16384)
#define H_OFF     (X_OFF + 12288)
#define SH        68
#define SMEM_BYTES (H_OFF + 64 * SH * 4)

static __device__ __forceinline__ float tanh_a(float x) {
    float y;
    asm("tanh.approx.f32 %0, %1;" : "=f"(y) : "f"(x));
    return y;
}
static __device__ __forceinline__ __half2 tanh2(__half2 x) {
    unsigned r, xi = *(unsigned*)&x;
    asm("tanh.approx.f16x2 %0, %1;" : "=r"(r) : "r"(xi));
    return *(__half2*)&r;
}
static __device__ __forceinline__ void mma_f16(
    float& d0, float& d1, float& d2, float& d3,
    unsigned a0, unsigned a1, unsigned a2, unsigned a3,
    unsigned b0, unsigned b1)
{
    asm volatile(
        "mma.sync.aligned.m16n8k16.row.col.f32.f16.f16.f32 "
        "{%0,%1,%2,%3}, {%4,%5,%6,%7}, {%8,%9}, {%0,%1,%2,%3};"
        : "+f"(d0), "+f"(d1), "+f"(d2), "+f"(d3)
        : "r"(a0), "r"(a1), "r"(a2), "r"(a3), "r"(b0), "r"(b1));
}

// fragment coordinates for feature index k within a 16-wide block
static __device__ __forceinline__ void bcoord(int k, int& kb, int& tqp, int& u) {
    kb = k >> 4;
    int km = k & 15;
    if (km < 8) { tqp = km >> 1;       u = km & 1; }
    else        { tqp = (km - 8) >> 1; u = 2 + (km & 1); }
}

__global__ __launch_bounds__(NT, 1)
void lstm_kernel(const float* __restrict__ x,
                 const float* __restrict__ W_ih, const float* __restrict__ W_hh,
                 const float* __restrict__ b_ih, const float* __restrict__ b_hh,
                 const float* __restrict__ W_fc, const float* __restrict__ b_fc,
                 float* __restrict__ out)
{
    extern __shared__ char smc[];
    char*  Abuf = smc;
    float* H    = (float*)(smc + H_OFF);

    const int tid  = threadIdx.x;
    const int lane = tid & 31;
    const int w    = tid >> 5;            // 8 warps; wm = w
    const int g    = lane >> 2;           // 0..7
    const int tq   = lane & 3;            // 0..3
    const int b0   = blockIdx.x * TB;

    // ---- one-time A fill (fp16, fragment-native layout) ----
    for (int idx = tid; idx < 256 * 96; idx += NT) {
        int p = idx / 96, k = idx - p * 96;
        int pwm = p >> 5, mt = (p >> 4) & 1, s = (p >> 3) & 1, pg = p & 7;
        int q = mt * 2 + s;
        int h = pwm * 8 + pg;
        int rl = q * 64 + h;
        float v = (k < 32) ? W_ih[rl * 32 + k] : W_hh[rl * 64 + (k - 32)];
        int kb, tqp, u;
        bcoord(k, kb, tqp, u);
        int hh = u >> 1, b = u & 1;
        int half_idx = (((((kb * 8 + pwm) * 2 + mt) * 8 + pg) * 4 + tqp) << 3)
                     + hh * 4 + s * 2 + b;
        *(__half*)(Abuf + half_idx * 2) = __float2half_rn(v);
    }
    // zero phase-0 h buffers of both groups (h_{-1} = 0)
    for (int idx = tid; idx < 1024; idx += NT) {
        ((unsigned*)(smc + BH_OFF))[idx]        = 0u;
        ((unsigned*)(smc + BH_OFF + 8192))[idx] = 0u;
    }

    // per-thread biases for hidden unit h_own
    const int h_own = w * 8 + g;
    const float bi = 0.5f * (b_ih[0 * 64 + h_own] + b_hh[0 * 64 + h_own]);
    const float bf = 0.5f * (b_ih[1 * 64 + h_own] + b_hh[1 * 64 + h_own]);
    const float bg =         b_ih[2 * 64 + h_own] + b_hh[2 * 64 + h_own];
    const float bo = 0.5f * (b_ih[3 * 64 + h_own] + b_hh[3 * 64 + h_own]);
    const __half2 bi2 = __float2half2_rn(bi);
    const __half2 bf2 = __float2half2_rn(bf);
    const __half2 bg2 = __float2half2_rn(bg);
    const __half2 bo2 = __float2half2_rn(bo);
    const __half2 h05 = __float2half2_rn(0.5f);

    // h write base within a group phase-buffer
    int hkb, htqp, hu;
    bcoord(h_own, hkb, htqp, hu);
    const int hbase = hkb * 1024 + (2 * tq) * 32 + htqp * 8 + hu * 2;

    float cA[8], cB[8];
#pragma unroll
    for (int j = 0; j < 8; ++j) { cA[j] = 0.0f; cB[j] = 0.0f; }
    float hlastA[8], hlastB[8];

    // x staging: 2 tasks per thread (task = tid, tid+256); task -> (batch cb, chunk hg)
    const float* xrow[2];
    char* xgb[2];
    int xo0[2], xo1[2];
    float4 xpref[2];
#pragma unroll
    for (int i = 0; i < 2; ++i) {
        int task = tid + i * 256;
        int cb = task >> 3, hg = task & 7;
        int gsel = cb >> 5, nloc = cb & 31;
        xrow[i] = x + ((size_t)(b0 + cb) * T_STEPS) * 32 + hg * 4;
        xgb[i]  = smc + X_OFF + gsel * 6144;
        int kb, tqp, u;
        bcoord(hg * 4 + 0, kb, tqp, u);
        xo0[i] = kb * 1024 + nloc * 32 + tqp * 8 + u * 2;
        bcoord(hg * 4 + 2, kb, tqp, u);
        xo1[i] = kb * 1024 + nloc * 32 + tqp * 8 + u * 2;
        // stage x_0 -> buf0, x_1 -> buf1
        float4 xv = *(const float4*)xrow[i];
        *(__half2*)(xgb[i] + xo0[i]) = __floats2half2_rn(xv.x, xv.y);
        *(__half2*)(xgb[i] + xo1[i]) = __floats2half2_rn(xv.z, xv.w);
        xv = *(const float4*)(xrow[i] + 32);
        *(__half2*)(xgb[i] + 2048 + xo0[i]) = __floats2half2_rn(xv.x, xv.y);
        *(__half2*)(xgb[i] + 2048 + xo1[i]) = __floats2half2_rn(xv.z, xv.w);
        xpref[i] = *(const float4*)(xrow[i] + 64);   // x_2
    }
    __syncthreads();

    // ---- load A fragments into registers (resident for the whole kernel) ----
    uint4 aF[6][2];
    {
        const char* pA = Abuf + w * 1024 + g * 64 + tq * 16;
#pragma unroll
        for (int kb = 0; kb < 6; ++kb)
#pragma unroll
            for (int mt = 0; mt < 2; ++mt)
                aF[kb][mt] = *(const uint4*)(pA + kb * 8192 + mt * 512);
    }

    const int fB = g * 32 + tq * 8;
    char* BhA = smc + BH_OFF;             // group 0 (batches 0..31)
    char* BhB = smc + BH_OFF + 8192;      // group 1 (batches 32..63)
    char* XA  = smc + X_OFF;
    char* XB  = smc + X_OFF + 6144;

    // accumulators: d[set][mt][nt][r]
    float dA[2][4][4], dB[2][4][4];
#pragma unroll
    for (int mt = 0; mt < 2; ++mt)
#pragma unroll
        for (int nt = 0; nt < 4; ++nt)
#pragma unroll
            for (int r = 0; r < 4; ++r) { dA[mt][nt][r] = 0.0f; dB[mt][nt][r] = 0.0f; }

    // prologue: d = Wx . x_0 (both sets)
#pragma unroll
    for (int kb = 0; kb < 2; ++kb)
#pragma unroll
        for (int nt = 0; nt < 4; ++nt) {
            uint2 bA = *(const uint2*)(XA + kb * 1024 + nt * 256 + fB);
            uint2 bB = *(const uint2*)(XB + kb * 1024 + nt * 256 + fB);
#pragma unroll
            for (int mt = 0; mt < 2; ++mt) {
                mma_f16(dA[mt][nt][0], dA[mt][nt][1], dA[mt][nt][2], dA[mt][nt][3],
                        aF[kb][mt].x, aF[kb][mt].y, aF[kb][mt].z, aF[kb][mt].w,
                        bA.x, bA.y);
                mma_f16(dB[mt][nt][0], dB[mt][nt][1], dB[mt][nt][2], dB[mt][nt][3],
                        aF[kb][mt].x, aF[kb][mt].y, aF[kb][mt].z, aF[kb][mt].w,
                        bB.x, bB.y);
            }
        }

    for (int t = 0; t < T_STEPS; ++t) {
        const char* bhA = BhA + (t & 1) * 4096;
        const char* bhB = BhB + (t & 1) * 4096;

        // ---- MMA_h: accumulate Wh . h_{t-1} for both sets (K = 64) ----
#pragma unroll
        for (int kb2 = 0; kb2 < 4; ++kb2)
#pragma unroll
            for (int nt = 0; nt < 4; ++nt) {
                uint2 bA = *(const uint2*)(bhA + kb2 * 1024 + nt * 256 + fB);
                uint2 bB = *(const uint2*)(bhB + kb2 * 1024 + nt * 256 + fB);
#pragma unroll
                for (int mt = 0; mt < 2; ++mt) {
                    mma_f16(dA[mt][nt][0], dA[mt][nt][1], dA[mt][nt][2], dA[mt][nt][3],
                            aF[2 + kb2][mt].x, aF[2 + kb2][mt].y,
                            aF[2 + kb2][mt].z, aF[2 + kb2][mt].w,
                            bA.x, bA.y);
                    mma_f16(dB[mt][nt][0], dB[mt][nt][1], dB[mt][nt][2], dB[mt][nt][3],
                            aF[2 + kb2][mt].x, aF[2 + kb2][mt].y,
                            aF[2 + kb2][mt].z, aF[2 + kb2][mt].w,
                            bB.x, bB.y);
                }
            }

        const bool last = (t + 1 == T_STEPS);

        if (!last) {
            char* bnA = BhA + ((t + 1) & 1) * 4096;
            char* bnB = BhB + ((t + 1) & 1) * 4096;

            // ---- packed-half epilogues (independent chains for A and B) ----
#pragma unroll
            for (int nt = 0; nt < 4; ++nt) {
                {
                    __half2 dih = __floats2half2_rn(dA[0][nt][0], dA[0][nt][1]);
                    __half2 dfh = __floats2half2_rn(dA[0][nt][2], dA[0][nt][3]);
                    __half2 dgh = __floats2half2_rn(dA[1][nt][0], dA[1][nt][1]);
                    __half2 doh = __floats2half2_rn(dA[1][nt][2], dA[1][nt][3]);
                    __half2 iv = __hfma2(tanh2(__hfma2(dih, h05, bi2)), h05, h05);
                    __half2 fv = __hfma2(tanh2(__hfma2(dfh, h05, bf2)), h05, h05);
                    __half2 gv = tanh2(__hadd2(dgh, bg2));
                    __half2 ov = __hfma2(tanh2(__hfma2(doh, h05, bo2)), h05, h05);
                    __half2 ig = __hmul2(iv, gv);
                    float cn0 = __low2float(fv)  * cA[2 * nt]     + __low2float(ig);
                    float cn1 = __high2float(fv) * cA[2 * nt + 1] + __high2float(ig);
                    cA[2 * nt] = cn0; cA[2 * nt + 1] = cn1;
                    __half2 hv = __hmul2(ov, tanh2(__floats2half2_rn(cn0, cn1)));
                    *(__half*)(bnA + hbase + nt * 256)      = __low2half(hv);
                    *(__half*)(bnA + hbase + nt * 256 + 32) = __high2half(hv);
                }
                {
                    __half2 dih = __floats2half2_rn(dB[0][nt][0], dB[0][nt][1]);
                    __half2 dfh = __floats2half2_rn(dB[0][nt][2], dB[0][nt][3]);
                    __half2 dgh = __floats2half2_rn(dB[1][nt][0], dB[1][nt][1]);
                    __half2 doh = __floats2half2_rn(dB[1][nt][2], dB[1][nt][3]);
                    __half2 iv = __hfma2(tanh2(__hfma2(dih, h05, bi2)), h05, h05);
                    __half2 fv = __hfma2(tanh2(__hfma2(dfh, h05, bf2)), h05, h05);
                    __half2 gv = tanh2(__hadd2(dgh, bg2));
                    __half2 ov = __hfma2(tanh2(__hfma2(doh, h05, bo2)), h05, h05);
                    __half2 ig = __hmul2(iv, gv);
                    float cn0 = __low2float(fv)  * cB[2 * nt]     + __low2float(ig);
                    float cn1 = __high2float(fv) * cB[2 * nt + 1] + __high2float(ig);
                    cB[2 * nt] = cn0; cB[2 * nt + 1] = cn1;
                    __half2 hv = __hmul2(ov, tanh2(__floats2half2_rn(cn0, cn1)));
                    *(__half*)(bnB + hbase + nt * 256)      = __low2half(hv);
                    *(__half*)(bnB + hbase + nt * 256 + 32) = __high2half(hv);
                }
            }

            // ---- refill tensor pipe: d = Wx . x_{t+1} (both sets) ----
#pragma unroll
            for (int mt = 0; mt < 2; ++mt)
#pragma unroll
                for (int nt = 0; nt < 4; ++nt)
#pragma unroll
                    for (int r = 0; r < 4; ++r) { dA[mt][nt][r] = 0.0f; dB[mt][nt][r] = 0.0f; }
            {
                const char* xbA = XA + ((t + 1) % 3) * 2048;
                const char* xbB = XB + ((t + 1) % 3) * 2048;
#pragma unroll
                for (int kb = 0; kb < 2; ++kb)
#pragma unroll
                    for (int nt = 0; nt < 4; ++nt) {
                        uint2 bA = *(const uint2*)(xbA + kb * 1024 + nt * 256 + fB);
                        uint2 bB = *(const uint2*)(xbB + kb * 1024 + nt * 256 + fB);
#pragma unroll
                        for (int mt = 0; mt < 2; ++mt) {
                            mma_f16(dA[mt][nt][0], dA[mt][nt][1], dA[mt][nt][2], dA[mt][nt][3],
                                    aF[kb][mt].x, aF[kb][mt].y, aF[kb][mt].z, aF[kb][mt].w,
                                    bA.x, bA.y);
                            mma_f16(dB[mt][nt][0], dB[mt][nt][1], dB[mt][nt][2], dB[mt][nt][3],
                                    aF[kb][mt].x, aF[kb][mt].y, aF[kb][mt].z, aF[kb][mt].w,
                                    bB.x, bB.y);
                        }
                    }
            }

            // ---- stage x_{t+2}, prefetch x_{t+3} ----
            if (t + 2 < T_STEPS) {
#pragma unroll
                for (int i = 0; i < 2; ++i) {
                    char* xn = xgb[i] + ((t + 2) % 3) * 2048;
                    *(__half2*)(xn + xo0[i]) = __floats2half2_rn(xpref[i].x, xpref[i].y);
                    *(__half2*)(xn + xo1[i]) = __floats2half2_rn(xpref[i].z, xpref[i].w);
                    if (t + 3 < T_STEPS)
                        xpref[i] = *(const float4*)(xrow[i] + (size_t)(t + 3) * 32);
                }
            }
        } else {
            // final step: fp32 epilogue for h_T precision (both sets)
#pragma unroll
            for (int nt = 0; nt < 4; ++nt)
#pragma unroll
                for (int bl = 0; bl < 2; ++bl) {
                    int j = nt * 2 + bl;
                    {
                        float iv = 0.5f + 0.5f * tanh_a(0.5f * dA[0][nt][bl]     + bi);
                        float fv = 0.5f + 0.5f * tanh_a(0.5f * dA[0][nt][2 + bl] + bf);
                        float gv =               tanh_a(       dA[1][nt][bl]     + bg);
                        float ov = 0.5f + 0.5f * tanh_a(0.5f * dA[1][nt][2 + bl] + bo);
                        float cn = fv * cA[j] + iv * gv;
                        hlastA[j] = ov * tanh_a(cn);
                    }
                    {
                        float iv = 0.5f + 0.5f * tanh_a(0.5f * dB[0][nt][bl]     + bi);
                        float fv = 0.5f + 0.5f * tanh_a(0.5f * dB[0][nt][2 + bl] + bf);
                        float gv =               tanh_a(       dB[1][nt][bl]     + bg);
                        float ov = 0.5f + 0.5f * tanh_a(0.5f * dB[1][nt][2 + bl] + bo);
                        float cn = fv * cB[j] + iv * gv;
                        hlastB[j] = ov * tanh_a(cn);
                    }
                }
        }
        __syncthreads();
    }

    // ---- stage h_T into H[batch][h], then FC ----
#pragma unroll
    for (int nt = 0; nt < 4; ++nt)
#pragma unroll
        for (int bl = 0; bl < 2; ++bl) {
            int colA = nt * 8 + 2 * tq + bl;
            int colB = 32 + colA;
            H[colA * SH + h_own] = hlastA[nt * 2 + bl];
            H[colB * SH + h_own] = hlastB[nt * 2 + bl];
        }
    __syncthreads();
#pragma unroll
    for (int i = 0; i < 2; ++i) {
        int task = tid + i * 256;
        int ob = task >> 3;
        int oo = task & 7;
        float s = b_fc[oo];
        const float* hr = &H[ob * SH];
#pragma unroll 8
        for (int h2 = 0; h2 < 64; ++h2)
            s += W_fc[oo * 64 + h2] * hr[h2];
        out[(size_t)(b0 + ob) * 8 + oo] = s;
    }
}

extern "C" void kernel_launch(void* const* d_in, const int* in_sizes, int n_in,
                              void* d_out, int out_size)
{
    const float* x    = (const float*)d_in[0];
    const float* W_ih = (const float*)d_in[1];
    const float* W_hh = (const float*)d_in[2];
    const float* b_ih = (const float*)d_in[3];
    const float* b_hh = (const float*)d_in[4];
    const float* W_fc = (const float*)d_in[5];
    const float* b_fc = (const float*)d_in[6];
    float* out = (float*)d_out;

    cudaFuncSetAttribute(lstm_kernel, cudaFuncAttributeMaxDynamicSharedMemorySize, SMEM_BYTES);
    lstm_kernel<<<BATCH / TB, NT, SMEM_BYTES>>>(x, W_ih, W_hh, b_ih, b_hh, W_fc, b_fc, out);
}